// round 1
// baseline (speedup 1.0000x reference)
#include <cuda_runtime.h>
#include <cuda_bf16.h>
#include <cstdint>

// Problem constants (from reference):
//   NNZ = 819200, NUM_SESS = 16384, ITEMS_NUM = 1000000, EMB_DIM = 64
// Inputs (metadata order): row_idx[i32, NNZ] (sorted), col_idx[i32, NNZ],
//   data_tensor[f32, NNZ], num_ids[i32, 1], embeddings[f32, ITEMS_NUM*64]
// Output: f32 [NUM_SESS * 64]

#define EMB_DIM 64
#define CHUNK 128            // nnz per 64-thread group
#define GROUPS_PER_BLOCK 4   // 256 threads per block

__global__ void __launch_bounds__(256, 8)
weighted_seg_sum_kernel(const int* __restrict__ row_idx,
                        const int* __restrict__ col_idx,
                        const float* __restrict__ data,
                        const float* __restrict__ emb,
                        float* __restrict__ out,
                        int nnz)
{
    const int group = (blockIdx.x * blockDim.x + threadIdx.x) >> 6;  // global 64-thread group
    const int dim   = threadIdx.x & 63;

    const int start = group * CHUNK;
    if (start >= nnz) return;
    const int end = min(start + CHUNK, nnz);

    float acc = 0.0f;
    int cur_row = __ldg(&row_idx[start]);

    int i = start;
    // Main unrolled-by-4 loop. start is CHUNK-aligned (CHUNK % 4 == 0), so
    // vectorized 16B loads of the index/weight arrays are aligned.
    for (; i + 4 <= end; i += 4) {
        // Broadcast loads: all 64 threads of the group read the same 16B.
        const int4   r4 = __ldg(reinterpret_cast<const int4*>(row_idx + i));
        const int4   c4 = __ldg(reinterpret_cast<const int4*>(col_idx + i));
        const float4 w4 = __ldg(reinterpret_cast<const float4*>(data + i));

        // Issue all 4 gather loads before consuming any -> MLP = 4.
        float e0 = __ldg(emb + (size_t)c4.x * EMB_DIM + dim);
        float e1 = __ldg(emb + (size_t)c4.y * EMB_DIM + dim);
        float e2 = __ldg(emb + (size_t)c4.z * EMB_DIM + dim);
        float e3 = __ldg(emb + (size_t)c4.w * EMB_DIM + dim);

        if (r4.x != cur_row) { atomicAdd(out + (size_t)cur_row * EMB_DIM + dim, acc); acc = 0.0f; cur_row = r4.x; }
        acc = fmaf(w4.x, e0, acc);
        if (r4.y != cur_row) { atomicAdd(out + (size_t)cur_row * EMB_DIM + dim, acc); acc = 0.0f; cur_row = r4.y; }
        acc = fmaf(w4.y, e1, acc);
        if (r4.z != cur_row) { atomicAdd(out + (size_t)cur_row * EMB_DIM + dim, acc); acc = 0.0f; cur_row = r4.z; }
        acc = fmaf(w4.z, e2, acc);
        if (r4.w != cur_row) { atomicAdd(out + (size_t)cur_row * EMB_DIM + dim, acc); acc = 0.0f; cur_row = r4.w; }
        acc = fmaf(w4.w, e3, acc);
    }
    // Scalar tail (only if nnz not a multiple of 4; NNZ=819200 is, but stay general).
    for (; i < end; ++i) {
        const int   r = __ldg(&row_idx[i]);
        const int   c = __ldg(&col_idx[i]);
        const float w = __ldg(&data[i]);
        const float e = __ldg(emb + (size_t)c * EMB_DIM + dim);
        if (r != cur_row) { atomicAdd(out + (size_t)cur_row * EMB_DIM + dim, acc); acc = 0.0f; cur_row = r; }
        acc = fmaf(w, e, acc);
    }

    // Final flush for this group.
    atomicAdd(out + (size_t)cur_row * EMB_DIM + dim, acc);
}

extern "C" void kernel_launch(void* const* d_in, const int* in_sizes, int n_in,
                              void* d_out, int out_size)
{
    const int*   row_idx = (const int*)  d_in[0];
    const int*   col_idx = (const int*)  d_in[1];
    const float* data    = (const float*)d_in[2];
    // d_in[3] = num_ids (scalar), not needed on device: out_size gives it.
    const float* emb     = (const float*)d_in[4];
    float*       out     = (float*)d_out;

    const int nnz = in_sizes[0];

    // Output is poisoned; we accumulate with atomics, so zero it first.
    cudaMemsetAsync(out, 0, (size_t)out_size * sizeof(float));

    const int groups = (nnz + CHUNK - 1) / CHUNK;
    const int blocks = (groups + GROUPS_PER_BLOCK - 1) / GROUPS_PER_BLOCK;
    weighted_seg_sum_kernel<<<blocks, GROUPS_PER_BLOCK * 64>>>(
        row_idx, col_idx, data, emb, out, nnz);
}